// round 2
// baseline (speedup 1.0000x reference)
#include <cuda_runtime.h>
#include <cstdint>

#define NN 100000
#define DD 64
#define EE 1600000

// ---------------- scratch (no allocs allowed) ----------------
__device__ __align__(16) float g_agg[NN * DD];
__device__ __align__(16) float g_h1[NN * DD];
__device__ float g_cnt[NN];
__device__ float g_inv[NN];
__device__ int   g_idx[2 * EE];   // normalized int32 [src | dst]
__device__ int   g_is64;

// ---------------- dtype detection: int64 indices have all-zero high words ----------------
__global__ void detect_kernel(const unsigned int* __restrict__ w) {
    int all0 = 1;
    #pragma unroll 8
    for (int i = 0; i < 128; i++) {
        if (w[2 * i + 1] != 0u) { all0 = 0; break; }
    }
    g_is64 = all0;
}

// ---------------- normalize indices to int32 ----------------
__global__ void convert_kernel(const void* __restrict__ ei, int* __restrict__ out, int total) {
    int i = blockIdx.x * blockDim.x + threadIdx.x;
    if (i >= total) return;
    if (g_is64) out[i] = (int)((const long long*)ei)[i];
    else        out[i] = ((const int*)ei)[i];
}

// ---------------- degree ----------------
__global__ void degree_kernel(const int* __restrict__ dst, float* __restrict__ cnt, int E) {
    int e = blockIdx.x * blockDim.x + threadIdx.x;
    if (e < E) atomicAdd(&cnt[dst[e]], 1.0f);
}

__global__ void inv_kernel(const float* __restrict__ cnt, float* __restrict__ inv, int n) {
    int i = blockIdx.x * blockDim.x + threadIdx.x;
    if (i < n) inv[i] = 1.0f / fmaxf(cnt[i], 1.0f);
}

// ---------------- scatter: agg[dst] += in[src]  (vector atomics) ----------------
__global__ void scatter_kernel(const float4* __restrict__ in,
                               const int* __restrict__ src,
                               const int* __restrict__ dst,
                               float* __restrict__ agg, int E) {
    int idx = blockIdx.x * blockDim.x + threadIdx.x;
    int e = idx >> 4;          // 16 float4 chunks per 64-float row
    if (e >= E) return;
    int c = idx & 15;
    int s = src[e];
    int d = dst[e];
    float4 v = in[s * 16 + c];
    float* p = agg + (size_t)d * 64 + c * 4;
    asm volatile("red.global.add.v4.f32 [%0], {%1, %2, %3, %4};"
                 :: "l"(p), "f"(v.x), "f"(v.y), "f"(v.z), "f"(v.w)
                 : "memory");
}

// ---------------- fused SAGE layer GEMM ----------------
// out[n] = PReLU(agg'[n]@wl^T + bl + h[n]@wr^T) + x[n]@ws^T + bs,  agg' = agg*inv
// block: 256 threads, 64 rows x 64 cols tile, 4x4 per-thread register tile.
#define SA_STRIDE 132   // 128 + 4 pad
#define SX_STRIDE 68    // 64 + 4 pad
#define SW_STRIDE 68
#define SMEM_BYTES ((64*SA_STRIDE + 64*SX_STRIDE + 128*SW_STRIDE + 64*SW_STRIDE + 3*64) * 4)

__global__ void __launch_bounds__(256, 2)
sage_gemm_kernel(const float* __restrict__ agg, const float* __restrict__ h,
                 const float* __restrict__ x, const float* __restrict__ inv,
                 const float* __restrict__ wl, const float* __restrict__ bl,
                 const float* __restrict__ wr, const float* __restrict__ ws,
                 const float* __restrict__ bs, const float* __restrict__ al,
                 float* __restrict__ out, int nrows) {
    extern __shared__ float sm[];
    float* sA  = sm;                       // [64][SA_STRIDE]: cols 0..63 agg*inv, 64..127 h
    float* sX  = sA + 64 * SA_STRIDE;      // [64][SX_STRIDE]
    float* sW1 = sX + 64 * SX_STRIDE;      // [128][SW_STRIDE] k-major: k<64 -> wl, k>=64 -> wr
    float* sW2 = sW1 + 128 * SW_STRIDE;    // [64][SW_STRIDE]  k-major ws
    float* sBL = sW2 + 64 * SW_STRIDE;
    float* sBS = sBL + 64;
    float* sAl = sBS + 64;

    int tid = threadIdx.x;
    int row0 = blockIdx.x * 64;

    // weights, transposed to k-major (global reads coalesced along k)
    for (int i = tid; i < 64 * 64; i += 256) {
        int k = i & 63, d = i >> 6;
        float vl = wl[d * 64 + k];
        float vr = wr[d * 64 + k];
        float vs = ws[d * 64 + k];
        sW1[k * SW_STRIDE + d]        = vl;
        sW1[(k + 64) * SW_STRIDE + d] = vr;
        sW2[k * SW_STRIDE + d]        = vs;
    }
    if (tid < 64) { sBL[tid] = bl[tid]; sBS[tid] = bs[tid]; sAl[tid] = al[tid]; }

    // input rows
    for (int i = tid; i < 64 * 64; i += 256) {
        int r = i >> 6, c = i & 63;
        int row = row0 + r;
        float va = 0.f, vh = 0.f, vx = 0.f;
        if (row < nrows) {
            float s = inv[row];
            va = agg[(size_t)row * 64 + c] * s;
            vh = h[(size_t)row * 64 + c];
            vx = x[(size_t)row * 64 + c];
        }
        sA[r * SA_STRIDE + c]      = va;
        sA[r * SA_STRIDE + 64 + c] = vh;
        sX[r * SX_STRIDE + c]      = vx;
    }
    __syncthreads();

    int tx = tid & 15, ty = tid >> 4;
    int c0 = tx * 4, r0 = ty * 4;

    float acc[4][4];
#pragma unroll
    for (int i = 0; i < 4; i++)
#pragma unroll
        for (int j = 0; j < 4; j++) acc[i][j] = 0.f;

    // phase 1: t = agg'@wl^T + h@wr^T   (K = 128 over concat)
#pragma unroll 4
    for (int k = 0; k < 128; k += 4) {
        float a0[4], a1[4], a2[4], a3[4];
        *(float4*)a0 = *(const float4*)(sA + (r0 + 0) * SA_STRIDE + k);
        *(float4*)a1 = *(const float4*)(sA + (r0 + 1) * SA_STRIDE + k);
        *(float4*)a2 = *(const float4*)(sA + (r0 + 2) * SA_STRIDE + k);
        *(float4*)a3 = *(const float4*)(sA + (r0 + 3) * SA_STRIDE + k);
#pragma unroll
        for (int u = 0; u < 4; u++) {
            float4 w = *(const float4*)(sW1 + (k + u) * SW_STRIDE + c0);
            acc[0][0] += a0[u] * w.x; acc[0][1] += a0[u] * w.y; acc[0][2] += a0[u] * w.z; acc[0][3] += a0[u] * w.w;
            acc[1][0] += a1[u] * w.x; acc[1][1] += a1[u] * w.y; acc[1][2] += a1[u] * w.z; acc[1][3] += a1[u] * w.w;
            acc[2][0] += a2[u] * w.x; acc[2][1] += a2[u] * w.y; acc[2][2] += a2[u] * w.z; acc[2][3] += a2[u] * w.w;
            acc[3][0] += a3[u] * w.x; acc[3][1] += a3[u] * w.y; acc[3][2] += a3[u] * w.z; acc[3][3] += a3[u] * w.w;
        }
    }

    // epilogue 1: bias + PReLU
#pragma unroll
    for (int j = 0; j < 4; j++) {
        float b = sBL[c0 + j];
        float a = sAl[c0 + j];
#pragma unroll
        for (int i = 0; i < 4; i++) {
            float t = acc[i][j] + b;
            acc[i][j] = (t >= 0.f) ? t : a * t;
        }
    }

    // phase 2: += x@ws^T  (K = 64)
#pragma unroll 4
    for (int k = 0; k < 64; k += 4) {
        float a0[4], a1[4], a2[4], a3[4];
        *(float4*)a0 = *(const float4*)(sX + (r0 + 0) * SX_STRIDE + k);
        *(float4*)a1 = *(const float4*)(sX + (r0 + 1) * SX_STRIDE + k);
        *(float4*)a2 = *(const float4*)(sX + (r0 + 2) * SX_STRIDE + k);
        *(float4*)a3 = *(const float4*)(sX + (r0 + 3) * SX_STRIDE + k);
#pragma unroll
        for (int u = 0; u < 4; u++) {
            float4 w = *(const float4*)(sW2 + (k + u) * SW_STRIDE + c0);
            acc[0][0] += a0[u] * w.x; acc[0][1] += a0[u] * w.y; acc[0][2] += a0[u] * w.z; acc[0][3] += a0[u] * w.w;
            acc[1][0] += a1[u] * w.x; acc[1][1] += a1[u] * w.y; acc[1][2] += a1[u] * w.z; acc[1][3] += a1[u] * w.w;
            acc[2][0] += a2[u] * w.x; acc[2][1] += a2[u] * w.y; acc[2][2] += a2[u] * w.z; acc[2][3] += a2[u] * w.w;
            acc[3][0] += a3[u] * w.x; acc[3][1] += a3[u] * w.y; acc[3][2] += a3[u] * w.z; acc[3][3] += a3[u] * w.w;
        }
    }

    // epilogue 2: + bs, vector store
#pragma unroll
    for (int i = 0; i < 4; i++) {
        int row = row0 + r0 + i;
        if (row < nrows) {
            float4 o;
            o.x = acc[i][0] + sBS[c0 + 0];
            o.y = acc[i][1] + sBS[c0 + 1];
            o.z = acc[i][2] + sBS[c0 + 2];
            o.w = acc[i][3] + sBS[c0 + 3];
            *(float4*)(out + (size_t)row * 64 + c0) = o;
        }
    }
}

// ---------------- launch ----------------
extern "C" void kernel_launch(void* const* d_in, const int* in_sizes, int n_in,
                              void* d_out, int out_size) {
    const float* x  = (const float*)d_in[0];
    const void*  ei = d_in[1];
    const float* wl0 = (const float*)d_in[2];
    const float* bl0 = (const float*)d_in[3];
    const float* wr0 = (const float*)d_in[4];
    const float* ws0 = (const float*)d_in[5];
    const float* bs0 = (const float*)d_in[6];
    const float* a0  = (const float*)d_in[7];
    const float* wl1 = (const float*)d_in[8];
    const float* bl1 = (const float*)d_in[9];
    const float* wr1 = (const float*)d_in[10];
    const float* ws1 = (const float*)d_in[11];
    const float* bs1 = (const float*)d_in[12];
    const float* a1  = (const float*)d_in[13];
    float* out = (float*)d_out;

    int N = in_sizes[0] / 64;
    int E = in_sizes[1] / 2;

    float *agg, *h1, *cnt, *inv;
    int *idx;
    cudaGetSymbolAddress((void**)&agg, g_agg);
    cudaGetSymbolAddress((void**)&h1,  g_h1);
    cudaGetSymbolAddress((void**)&cnt, g_cnt);
    cudaGetSymbolAddress((void**)&inv, g_inv);
    cudaGetSymbolAddress((void**)&idx, g_idx);

    cudaFuncSetAttribute(sage_gemm_kernel, cudaFuncAttributeMaxDynamicSharedMemorySize, SMEM_BYTES);

    // normalize edge indices to int32 (handles int64- or int32-delivered buffers)
    detect_kernel<<<1, 1>>>((const unsigned int*)ei);
    int total = 2 * E;
    convert_kernel<<<(total + 255) / 256, 256>>>(ei, idx, total);

    const int* src = idx;
    const int* dst = idx + E;

    // degree (shared by both layers)
    cudaMemsetAsync(cnt, 0, (size_t)N * sizeof(float), 0);
    cudaMemsetAsync(agg, 0, (size_t)N * 64 * sizeof(float), 0);
    degree_kernel<<<(E + 255) / 256, 256>>>(dst, cnt, E);
    inv_kernel<<<(N + 255) / 256, 256>>>(cnt, inv, N);

    // layer 0: aggregate x
    long long nscatter = (long long)E * 16;
    int sblocks = (int)((nscatter + 255) / 256);
    scatter_kernel<<<sblocks, 256>>>((const float4*)x, src, dst, agg, E);
    sage_gemm_kernel<<<(N + 63) / 64, 256, SMEM_BYTES>>>(
        agg, x, x, inv, wl0, bl0, wr0, ws0, bs0, a0, h1, N);

    // layer 1: aggregate h1
    cudaMemsetAsync(agg, 0, (size_t)N * 64 * sizeof(float), 0);
    scatter_kernel<<<sblocks, 256>>>((const float4*)h1, src, dst, agg, E);
    sage_gemm_kernel<<<(N + 63) / 64, 256, SMEM_BYTES>>>(
        agg, h1, x, inv, wl1, bl1, wr1, ws1, bs1, a1, out, N);
}

// round 3
// speedup vs baseline: 1.8038x; 1.8038x over previous
#include <cuda_runtime.h>
#include <cstdint>

#define NN 100000
#define DD 64
#define EE 1600000
#define NB_SCAN ((NN + 1023) / 1024)

// ---------------- scratch (no allocs allowed) ----------------
__device__ __align__(16) float g_agg[NN * DD];
__device__ __align__(16) float g_h1[NN * DD];
__device__ int   g_deg[NN];
__device__ int   g_wcnt[NN];
__device__ int   g_rp[NN + 1];
__device__ float g_inv[NN];
__device__ int   g_idx[2 * EE];   // normalized int32 [src | dst]
__device__ int   g_csr[EE];       // src ids grouped by dst
__device__ int   g_bsum[128];
__device__ int   g_is64;

// ---------------- dtype detection: int64 indices have all-zero high words ----------------
__global__ void detect_kernel(const unsigned int* __restrict__ w) {
    int all0 = 1;
    #pragma unroll 8
    for (int i = 0; i < 128; i++) {
        if (w[2 * i + 1] != 0u) { all0 = 0; break; }
    }
    g_is64 = all0;
}

// ---------------- normalize indices to int32 ----------------
__global__ void convert_kernel(const void* __restrict__ ei, int* __restrict__ out, int total) {
    int i = blockIdx.x * blockDim.x + threadIdx.x;
    if (i >= total) return;
    if (g_is64) out[i] = (int)((const long long*)ei)[i];
    else        out[i] = ((const int*)ei)[i];
}

// ---------------- degree histogram ----------------
__global__ void degree_kernel(const int* __restrict__ dst, int* __restrict__ deg, int E) {
    int e = blockIdx.x * blockDim.x + threadIdx.x;
    if (e < E) atomicAdd(&deg[dst[e]], 1);
}

__global__ void inv_kernel(const int* __restrict__ deg, float* __restrict__ inv, int n) {
    int i = blockIdx.x * blockDim.x + threadIdx.x;
    if (i < n) inv[i] = 1.0f / (float)max(deg[i], 1);
}

// ---------------- 3-kernel exclusive scan (1024 elems / block) ----------------
__global__ void scan1_kernel(const int* __restrict__ deg, int* __restrict__ rp,
                             int* __restrict__ bsum, int n) {
    __shared__ int wsum[8];
    int t = threadIdx.x;
    int base = blockIdx.x * 1024 + t * 4;
    int v[4];
#pragma unroll
    for (int j = 0; j < 4; j++) v[j] = (base + j < n) ? deg[base + j] : 0;
    int tot = v[0] + v[1] + v[2] + v[3];
    int lane = t & 31, w = t >> 5;
    int inc = tot;
#pragma unroll
    for (int d = 1; d < 32; d <<= 1) {
        int o = __shfl_up_sync(0xffffffffu, inc, d);
        if (lane >= d) inc += o;
    }
    if (lane == 31) wsum[w] = inc;
    __syncthreads();
    if (t == 0) {
        int r = 0;
#pragma unroll
        for (int i = 0; i < 8; i++) { int x = wsum[i]; wsum[i] = r; r += x; }
    }
    __syncthreads();
    int excl = wsum[w] + inc - tot;
    int r = excl;
#pragma unroll
    for (int j = 0; j < 4; j++) {
        if (base + j < n) rp[base + j] = r;
        r += v[j];
    }
    if (t == 255) bsum[blockIdx.x] = wsum[7] + inc;   // block total
}

__global__ void scan2_kernel(int* __restrict__ bsum, int nb, int* __restrict__ rp, int n) {
    if (threadIdx.x == 0) {
        int r = 0;
        for (int i = 0; i < nb; i++) { int x = bsum[i]; bsum[i] = r; r += x; }
        rp[n] = r;
    }
}

__global__ void scan3_kernel(int* __restrict__ rp, const int* __restrict__ bsum, int n) {
    int i = blockIdx.x * blockDim.x + threadIdx.x;
    if (i < n) rp[i] += bsum[i >> 10];
}

// ---------------- CSR placement ----------------
__global__ void place_kernel(const int* __restrict__ src, const int* __restrict__ dst,
                             const int* __restrict__ rp, int* __restrict__ wcnt,
                             int* __restrict__ csr, int E) {
    int e = blockIdx.x * blockDim.x + threadIdx.x;
    if (e >= E) return;
    int d = dst[e];
    int p = rp[d] + atomicAdd(&wcnt[d], 1);
    csr[p] = src[e];
}

// ---------------- CSR mean-gather: agg[node] = (1/deg) * sum_{s in nbr} in[s] ----------------
// one warp per node; lane owns 2 floats (float2); neighbor ids broadcast via shfl.
__global__ void __launch_bounds__(256)
gather_kernel(const float2* __restrict__ in, const int* __restrict__ rp,
              const int* __restrict__ csr, const float* __restrict__ inv,
              float2* __restrict__ agg, int n) {
    int wid = (blockIdx.x * blockDim.x + threadIdx.x) >> 5;
    if (wid >= n) return;
    int lane = threadIdx.x & 31;
    int start = rp[wid], end = rp[wid + 1];
    float2 acc = {0.f, 0.f};
    for (int base = start; base < end; base += 32) {
        int nn = min(32, end - base);
        int s = (lane < nn) ? csr[base + lane] : 0;
        int j = 0;
        for (; j + 4 <= nn; j += 4) {
            int s0 = __shfl_sync(0xffffffffu, s, j + 0);
            int s1 = __shfl_sync(0xffffffffu, s, j + 1);
            int s2 = __shfl_sync(0xffffffffu, s, j + 2);
            int s3 = __shfl_sync(0xffffffffu, s, j + 3);
            float2 v0 = in[(size_t)s0 * 32 + lane];
            float2 v1 = in[(size_t)s1 * 32 + lane];
            float2 v2 = in[(size_t)s2 * 32 + lane];
            float2 v3 = in[(size_t)s3 * 32 + lane];
            acc.x += v0.x + v1.x + v2.x + v3.x;
            acc.y += v0.y + v1.y + v2.y + v3.y;
        }
        for (; j < nn; j++) {
            int sj = __shfl_sync(0xffffffffu, s, j);
            float2 v = in[(size_t)sj * 32 + lane];
            acc.x += v.x; acc.y += v.y;
        }
    }
    float iv = inv[wid];
    acc.x *= iv; acc.y *= iv;
    agg[(size_t)wid * 32 + lane] = acc;
}

// ---------------- fused SAGE layer GEMM ----------------
// out[n] = PReLU(agg[n]@wl^T + bl + h[n]@wr^T) + x[n]@ws^T + bs    (agg already mean-scaled)
#define SA_STRIDE 132   // 128 + 4 pad
#define SX_STRIDE 68    // 64 + 4 pad
#define SW_STRIDE 68
#define SMEM_BYTES ((64*SA_STRIDE + 64*SX_STRIDE + 128*SW_STRIDE + 64*SW_STRIDE + 3*64) * 4)

__global__ void __launch_bounds__(256, 2)
sage_gemm_kernel(const float* __restrict__ agg, const float* __restrict__ h,
                 const float* __restrict__ x,
                 const float* __restrict__ wl, const float* __restrict__ bl,
                 const float* __restrict__ wr, const float* __restrict__ ws,
                 const float* __restrict__ bs, const float* __restrict__ al,
                 float* __restrict__ out, int nrows) {
    extern __shared__ float sm[];
    float* sA  = sm;                       // [64][SA_STRIDE]: cols 0..63 agg, 64..127 h
    float* sX  = sA + 64 * SA_STRIDE;      // [64][SX_STRIDE]
    float* sW1 = sX + 64 * SX_STRIDE;      // [128][SW_STRIDE] k-major: k<64 wl, k>=64 wr
    float* sW2 = sW1 + 128 * SW_STRIDE;    // [64][SW_STRIDE] ws
    float* sBL = sW2 + 64 * SW_STRIDE;
    float* sBS = sBL + 64;
    float* sAl = sBS + 64;

    int tid = threadIdx.x;
    int row0 = blockIdx.x * 64;

    for (int i = tid; i < 64 * 64; i += 256) {
        int k = i & 63, d = i >> 6;
        sW1[k * SW_STRIDE + d]        = wl[d * 64 + k];
        sW1[(k + 64) * SW_STRIDE + d] = wr[d * 64 + k];
        sW2[k * SW_STRIDE + d]        = ws[d * 64 + k];
    }
    if (tid < 64) { sBL[tid] = bl[tid]; sBS[tid] = bs[tid]; sAl[tid] = al[tid]; }

    for (int i = tid; i < 64 * 64; i += 256) {
        int r = i >> 6, c = i & 63;
        int row = row0 + r;
        float va = 0.f, vh = 0.f, vx = 0.f;
        if (row < nrows) {
            va = agg[(size_t)row * 64 + c];
            vh = h[(size_t)row * 64 + c];
            vx = x[(size_t)row * 64 + c];
        }
        sA[r * SA_STRIDE + c]      = va;
        sA[r * SA_STRIDE + 64 + c] = vh;
        sX[r * SX_STRIDE + c]      = vx;
    }
    __syncthreads();

    int tx = tid & 15, ty = tid >> 4;
    int c0 = tx * 4, r0 = ty * 4;

    float acc[4][4];
#pragma unroll
    for (int i = 0; i < 4; i++)
#pragma unroll
        for (int j = 0; j < 4; j++) acc[i][j] = 0.f;

#pragma unroll 4
    for (int k = 0; k < 128; k += 4) {
        float a0[4], a1[4], a2[4], a3[4];
        *(float4*)a0 = *(const float4*)(sA + (r0 + 0) * SA_STRIDE + k);
        *(float4*)a1 = *(const float4*)(sA + (r0 + 1) * SA_STRIDE + k);
        *(float4*)a2 = *(const float4*)(sA + (r0 + 2) * SA_STRIDE + k);
        *(float4*)a3 = *(const float4*)(sA + (r0 + 3) * SA_STRIDE + k);
#pragma unroll
        for (int u = 0; u < 4; u++) {
            float4 w = *(const float4*)(sW1 + (k + u) * SW_STRIDE + c0);
            acc[0][0] += a0[u] * w.x; acc[0][1] += a0[u] * w.y; acc[0][2] += a0[u] * w.z; acc[0][3] += a0[u] * w.w;
            acc[1][0] += a1[u] * w.x; acc[1][1] += a1[u] * w.y; acc[1][2] += a1[u] * w.z; acc[1][3] += a1[u] * w.w;
            acc[2][0] += a2[u] * w.x; acc[2][1] += a2[u] * w.y; acc[2][2] += a2[u] * w.z; acc[2][3] += a2[u] * w.w;
            acc[3][0] += a3[u] * w.x; acc[3][1] += a3[u] * w.y; acc[3][2] += a3[u] * w.z; acc[3][3] += a3[u] * w.w;
        }
    }

#pragma unroll
    for (int j = 0; j < 4; j++) {
        float b = sBL[c0 + j];
        float a = sAl[c0 + j];
#pragma unroll
        for (int i = 0; i < 4; i++) {
            float t = acc[i][j] + b;
            acc[i][j] = (t >= 0.f) ? t : a * t;
        }
    }

#pragma unroll 4
    for (int k = 0; k < 64; k += 4) {
        float a0[4], a1[4], a2[4], a3[4];
        *(float4*)a0 = *(const float4*)(sX + (r0 + 0) * SX_STRIDE + k);
        *(float4*)a1 = *(const float4*)(sX + (r0 + 1) * SX_STRIDE + k);
        *(float4*)a2 = *(const float4*)(sX + (r0 + 2) * SX_STRIDE + k);
        *(float4*)a3 = *(const float4*)(sX + (r0 + 3) * SX_STRIDE + k);
#pragma unroll
        for (int u = 0; u < 4; u++) {
            float4 w = *(const float4*)(sW2 + (k + u) * SW_STRIDE + c0);
            acc[0][0] += a0[u] * w.x; acc[0][1] += a0[u] * w.y; acc[0][2] += a0[u] * w.z; acc[0][3] += a0[u] * w.w;
            acc[1][0] += a1[u] * w.x; acc[1][1] += a1[u] * w.y; acc[1][2] += a1[u] * w.z; acc[1][3] += a1[u] * w.w;
            acc[2][0] += a2[u] * w.x; acc[2][1] += a2[u] * w.y; acc[2][2] += a2[u] * w.z; acc[2][3] += a2[u] * w.w;
            acc[3][0] += a3[u] * w.x; acc[3][1] += a3[u] * w.y; acc[3][2] += a3[u] * w.z; acc[3][3] += a3[u] * w.w;
        }
    }

#pragma unroll
    for (int i = 0; i < 4; i++) {
        int row = row0 + r0 + i;
        if (row < nrows) {
            float4 o;
            o.x = acc[i][0] + sBS[c0 + 0];
            o.y = acc[i][1] + sBS[c0 + 1];
            o.z = acc[i][2] + sBS[c0 + 2];
            o.w = acc[i][3] + sBS[c0 + 3];
            *(float4*)(out + (size_t)row * 64 + c0) = o;
        }
    }
}

// ---------------- launch ----------------
extern "C" void kernel_launch(void* const* d_in, const int* in_sizes, int n_in,
                              void* d_out, int out_size) {
    const float* x  = (const float*)d_in[0];
    const void*  ei = d_in[1];
    const float* wl0 = (const float*)d_in[2];
    const float* bl0 = (const float*)d_in[3];
    const float* wr0 = (const float*)d_in[4];
    const float* ws0 = (const float*)d_in[5];
    const float* bs0 = (const float*)d_in[6];
    const float* a0  = (const float*)d_in[7];
    const float* wl1 = (const float*)d_in[8];
    const float* bl1 = (const float*)d_in[9];
    const float* wr1 = (const float*)d_in[10];
    const float* ws1 = (const float*)d_in[11];
    const float* bs1 = (const float*)d_in[12];
    const float* a1  = (const float*)d_in[13];
    float* out = (float*)d_out;

    int N = in_sizes[0] / 64;
    int E = in_sizes[1] / 2;

    float *agg, *h1, *inv;
    int *deg, *wcnt, *rp, *idx, *csr, *bsum;
    cudaGetSymbolAddress((void**)&agg,  g_agg);
    cudaGetSymbolAddress((void**)&h1,   g_h1);
    cudaGetSymbolAddress((void**)&deg,  g_deg);
    cudaGetSymbolAddress((void**)&wcnt, g_wcnt);
    cudaGetSymbolAddress((void**)&rp,   g_rp);
    cudaGetSymbolAddress((void**)&inv,  g_inv);
    cudaGetSymbolAddress((void**)&idx,  g_idx);
    cudaGetSymbolAddress((void**)&csr,  g_csr);
    cudaGetSymbolAddress((void**)&bsum, g_bsum);

    cudaFuncSetAttribute(sage_gemm_kernel, cudaFuncAttributeMaxDynamicSharedMemorySize, SMEM_BYTES);

    // normalize edge indices to int32
    detect_kernel<<<1, 1>>>((const unsigned int*)ei);
    int total = 2 * E;
    convert_kernel<<<(total + 255) / 256, 256>>>(ei, idx, total);

    const int* src = idx;
    const int* dst = idx + E;

    // CSR build
    cudaMemsetAsync(deg,  0, (size_t)N * sizeof(int), 0);
    cudaMemsetAsync(wcnt, 0, (size_t)N * sizeof(int), 0);
    degree_kernel<<<(E + 255) / 256, 256>>>(dst, deg, E);
    inv_kernel<<<(N + 255) / 256, 256>>>(deg, inv, N);
    int nb = (N + 1023) / 1024;
    scan1_kernel<<<nb, 256>>>(deg, rp, bsum, N);
    scan2_kernel<<<1, 32>>>(bsum, nb, rp, N);
    scan3_kernel<<<(N + 255) / 256, 256>>>(rp, bsum, N);
    place_kernel<<<(E + 255) / 256, 256>>>(src, dst, rp, wcnt, csr, E);

    int gather_blocks = (N * 32 + 255) / 256;

    // layer 0
    gather_kernel<<<gather_blocks, 256>>>((const float2*)x, rp, csr, inv, (float2*)agg, N);
    sage_gemm_kernel<<<(N + 63) / 64, 256, SMEM_BYTES>>>(
        agg, x, x, wl0, bl0, wr0, ws0, bs0, a0, h1, N);

    // layer 1
    gather_kernel<<<gather_blocks, 256>>>((const float2*)h1, rp, csr, inv, (float2*)agg, N);
    sage_gemm_kernel<<<(N + 63) / 64, 256, SMEM_BYTES>>>(
        agg, h1, x, wl1, bl1, wr1, ws1, bs1, a1, out, N);
}

// round 4
// speedup vs baseline: 2.5646x; 1.4218x over previous
#include <cuda_runtime.h>
#include <cstdint>

#define NN 100000
#define DD 64
#define EE 1600000

// ---------------- scratch (no allocs allowed) ----------------
__device__ __align__(16) float g_agg[NN * DD];
__device__ __align__(16) float g_h1[NN * DD];
__device__ int   g_deg[NN];
__device__ int   g_wcnt[NN];
__device__ int   g_rp[NN + 1];
__device__ float g_inv[NN];
__device__ int   g_idx[2 * EE];   // normalized int32 [src | dst]
__device__ int   g_csr[EE];       // src ids grouped by dst
__device__ int   g_bsum[128];
__device__ int   g_is64;

// ---------------- dtype detection: int64 indices have all-zero high words ----------------
__global__ void detect_kernel(const unsigned int* __restrict__ w) {
    int all0 = 1;
    #pragma unroll 8
    for (int i = 0; i < 128; i++) {
        if (w[2 * i + 1] != 0u) { all0 = 0; break; }
    }
    g_is64 = all0;
}

__global__ void convert_kernel(const void* __restrict__ ei, int* __restrict__ out, int total) {
    int i = blockIdx.x * blockDim.x + threadIdx.x;
    if (i >= total) return;
    if (g_is64) out[i] = (int)((const long long*)ei)[i];
    else        out[i] = ((const int*)ei)[i];
}

// ---------------- degree histogram ----------------
__global__ void degree_kernel(const int* __restrict__ dst, int* __restrict__ deg, int E) {
    int e = blockIdx.x * blockDim.x + threadIdx.x;
    if (e < E) atomicAdd(&deg[dst[e]], 1);
}

__global__ void inv_kernel(const int* __restrict__ deg, float* __restrict__ inv, int n) {
    int i = blockIdx.x * blockDim.x + threadIdx.x;
    if (i < n) inv[i] = 1.0f / (float)max(deg[i], 1);
}

// ---------------- 3-kernel exclusive scan (1024 elems / block) ----------------
__global__ void scan1_kernel(const int* __restrict__ deg, int* __restrict__ rp,
                             int* __restrict__ bsum, int n) {
    __shared__ int wsum[8];
    int t = threadIdx.x;
    int base = blockIdx.x * 1024 + t * 4;
    int v[4];
#pragma unroll
    for (int j = 0; j < 4; j++) v[j] = (base + j < n) ? deg[base + j] : 0;
    int tot = v[0] + v[1] + v[2] + v[3];
    int lane = t & 31, w = t >> 5;
    int inc = tot;
#pragma unroll
    for (int d = 1; d < 32; d <<= 1) {
        int o = __shfl_up_sync(0xffffffffu, inc, d);
        if (lane >= d) inc += o;
    }
    if (lane == 31) wsum[w] = inc;
    __syncthreads();
    if (t == 0) {
        int r = 0;
#pragma unroll
        for (int i = 0; i < 8; i++) { int x = wsum[i]; wsum[i] = r; r += x; }
    }
    __syncthreads();
    int excl = wsum[w] + inc - tot;
    int r = excl;
#pragma unroll
    for (int j = 0; j < 4; j++) {
        if (base + j < n) rp[base + j] = r;
        r += v[j];
    }
    if (t == 255) bsum[blockIdx.x] = wsum[7] + inc;
}

__global__ void scan2_kernel(int* __restrict__ bsum, int nb, int* __restrict__ rp, int n) {
    if (threadIdx.x == 0) {
        int r = 0;
        for (int i = 0; i < nb; i++) { int x = bsum[i]; bsum[i] = r; r += x; }
        rp[n] = r;
    }
}

__global__ void scan3_kernel(int* __restrict__ rp, const int* __restrict__ bsum, int n) {
    int i = blockIdx.x * blockDim.x + threadIdx.x;
    if (i < n) rp[i] += bsum[i >> 10];
}

// ---------------- CSR placement ----------------
__global__ void place_kernel(const int* __restrict__ src, const int* __restrict__ dst,
                             const int* __restrict__ rp, int* __restrict__ wcnt,
                             int* __restrict__ csr, int E) {
    int e = blockIdx.x * blockDim.x + threadIdx.x;
    if (e >= E) return;
    int d = dst[e];
    int p = rp[d] + atomicAdd(&wcnt[d], 1);
    csr[p] = src[e];
}

// ---------------- CSR mean-gather ----------------
__global__ void __launch_bounds__(256)
gather_kernel(const float2* __restrict__ in, const int* __restrict__ rp,
              const int* __restrict__ csr, const float* __restrict__ inv,
              float2* __restrict__ agg, int n) {
    int wid = (blockIdx.x * blockDim.x + threadIdx.x) >> 5;
    if (wid >= n) return;
    int lane = threadIdx.x & 31;
    int start = rp[wid], end = rp[wid + 1];
    float2 acc = {0.f, 0.f};
    for (int base = start; base < end; base += 32) {
        int nn = min(32, end - base);
        int s = (lane < nn) ? csr[base + lane] : 0;
        int j = 0;
        for (; j + 4 <= nn; j += 4) {
            int s0 = __shfl_sync(0xffffffffu, s, j + 0);
            int s1 = __shfl_sync(0xffffffffu, s, j + 1);
            int s2 = __shfl_sync(0xffffffffu, s, j + 2);
            int s3 = __shfl_sync(0xffffffffu, s, j + 3);
            float2 v0 = in[(size_t)s0 * 32 + lane];
            float2 v1 = in[(size_t)s1 * 32 + lane];
            float2 v2 = in[(size_t)s2 * 32 + lane];
            float2 v3 = in[(size_t)s3 * 32 + lane];
            acc.x += v0.x + v1.x + v2.x + v3.x;
            acc.y += v0.y + v1.y + v2.y + v3.y;
        }
        for (; j < nn; j++) {
            int sj = __shfl_sync(0xffffffffu, s, j);
            float2 v = in[(size_t)sj * 32 + lane];
            acc.x += v.x; acc.y += v.y;
        }
    }
    float iv = inv[wid];
    acc.x *= iv; acc.y *= iv;
    agg[(size_t)wid * 32 + lane] = acc;
}

// ---------------- tf32 helpers ----------------
__device__ __forceinline__ unsigned int f2tf(float v) {
    unsigned int r;
    asm("cvt.rna.tf32.f32 %0, %1;" : "=r"(r) : "f"(v));
    return r;
}

__device__ __forceinline__ void mma_tf32(float c[4], unsigned int a0, unsigned int a1,
                                         unsigned int a2, unsigned int a3,
                                         unsigned int b0, unsigned int b1) {
    asm volatile(
        "mma.sync.aligned.m16n8k8.row.col.f32.tf32.tf32.f32 "
        "{%0,%1,%2,%3}, {%4,%5,%6,%7}, {%8,%9}, {%0,%1,%2,%3};"
        : "+f"(c[0]), "+f"(c[1]), "+f"(c[2]), "+f"(c[3])
        : "r"(a0), "r"(a1), "r"(a2), "r"(a3), "r"(b0), "r"(b1));
}

// ---------------- fused SAGE layer GEMM (tensor core, tf32) ----------------
// out[n] = PReLU(agg[n]@wl^T + bl + h[n]@wr^T) + x[n]@ws^T + bs
// block: 64 rows, 256 threads (8 warps in 4x2: 16 rows x 32 cols per warp)
#define SA_STRIDE 132   // 128 + 4; mod 32 = 4 -> conflict-free A frags
#define SX_STRIDE 68    // 64 + 4;  mod 32 = 4
#define SW_STRIDE 72    // 64 + 8;  mod 32 = 8 -> conflict-free B frags
#define SMEM_FLOATS (64*SA_STRIDE + 64*SX_STRIDE + 128*SW_STRIDE + 64*SW_STRIDE + 3*64)
#define SMEM_BYTES (SMEM_FLOATS * 4)

__global__ void __launch_bounds__(256, 2)
sage_gemm_kernel(const float* __restrict__ agg, const float* __restrict__ h,
                 const float* __restrict__ x,
                 const float* __restrict__ wl, const float* __restrict__ bl,
                 const float* __restrict__ wr, const float* __restrict__ ws,
                 const float* __restrict__ bs, const float* __restrict__ al,
                 float* __restrict__ out, int nrows) {
    extern __shared__ float sm[];
    float* sA  = sm;                       // [64][SA_STRIDE] tf32: cols 0..63 agg, 64..127 h
    float* sX  = sA + 64 * SA_STRIDE;      // [64][SX_STRIDE] tf32
    float* sW1 = sX + 64 * SX_STRIDE;      // [128][SW_STRIDE] tf32 k-major: k<64 wl, k>=64 wr
    float* sW2 = sW1 + 128 * SW_STRIDE;    // [64][SW_STRIDE]  tf32 ws
    float* sBL = sW2 + 64 * SW_STRIDE;
    float* sBS = sBL + 64;
    float* sAl = sBS + 64;

    int tid = threadIdx.x;
    int row0 = blockIdx.x * 64;

    // stage weights k-major, converted to tf32
    for (int i = tid; i < 64 * 64; i += 256) {
        int k = i & 63, d = i >> 6;
        ((unsigned int*)sW1)[k * SW_STRIDE + d]        = f2tf(wl[d * 64 + k]);
        ((unsigned int*)sW1)[(k + 64) * SW_STRIDE + d] = f2tf(wr[d * 64 + k]);
        ((unsigned int*)sW2)[k * SW_STRIDE + d]        = f2tf(ws[d * 64 + k]);
    }
    if (tid < 64) { sBL[tid] = bl[tid]; sBS[tid] = bs[tid]; sAl[tid] = al[tid]; }

    // stage input rows (vectorized), converted to tf32
    for (int i = tid; i < 64 * 16; i += 256) {
        int r = i >> 4, c4 = i & 15;
        int row = row0 + r;
        float4 va = {0.f,0.f,0.f,0.f}, vh = va, vx = va;
        if (row < nrows) {
            va = ((const float4*)agg)[(size_t)row * 16 + c4];
            vh = ((const float4*)h)[(size_t)row * 16 + c4];
            vx = ((const float4*)x)[(size_t)row * 16 + c4];
        }
        uint4 ta = {f2tf(va.x), f2tf(va.y), f2tf(va.z), f2tf(va.w)};
        uint4 th = {f2tf(vh.x), f2tf(vh.y), f2tf(vh.z), f2tf(vh.w)};
        uint4 tx_ = {f2tf(vx.x), f2tf(vx.y), f2tf(vx.z), f2tf(vx.w)};
        *(uint4*)(sA + r * SA_STRIDE + c4 * 4)      = ta;
        *(uint4*)(sA + r * SA_STRIDE + 64 + c4 * 4) = th;
        *(uint4*)(sX + r * SX_STRIDE + c4 * 4)      = tx_;
    }
    __syncthreads();

    int wid = tid >> 5, lane = tid & 31;
    int wy = wid >> 1, wx = wid & 1;          // 4 row groups x 2 col groups
    int mrow = wy * 16;                        // warp row base (within tile)
    int ncol = wx * 32;                        // warp col base
    int g = lane >> 2, tc = lane & 3;          // fragment group / quad

    float acc[4][4];                           // [ntile][reg]
#pragma unroll
    for (int t = 0; t < 4; t++)
#pragma unroll
        for (int r = 0; r < 4; r++) acc[t][r] = 0.f;

    const unsigned int* uA  = (const unsigned int*)sA;
    const unsigned int* uX  = (const unsigned int*)sX;
    const unsigned int* uW1 = (const unsigned int*)sW1;
    const unsigned int* uW2 = (const unsigned int*)sW2;

    // phase 1: agg@wl^T + h@wr^T  (K = 128)
#pragma unroll
    for (int k = 0; k < 128; k += 8) {
        unsigned int a0 = uA[(mrow + g) * SA_STRIDE + k + tc];
        unsigned int a1 = uA[(mrow + g + 8) * SA_STRIDE + k + tc];
        unsigned int a2 = uA[(mrow + g) * SA_STRIDE + k + tc + 4];
        unsigned int a3 = uA[(mrow + g + 8) * SA_STRIDE + k + tc + 4];
#pragma unroll
        for (int t = 0; t < 4; t++) {
            int nb = ncol + t * 8;
            unsigned int b0 = uW1[(k + tc) * SW_STRIDE + nb + g];
            unsigned int b1 = uW1[(k + tc + 4) * SW_STRIDE + nb + g];
            mma_tf32(acc[t], a0, a1, a2, a3, b0, b1);
        }
    }

    // epilogue 1: bias + PReLU
#pragma unroll
    for (int t = 0; t < 4; t++) {
        int col = ncol + t * 8 + tc * 2;
        float b0v = sBL[col], b1v = sBL[col + 1];
        float a0v = sAl[col], a1v = sAl[col + 1];
        float v;
        v = acc[t][0] + b0v; acc[t][0] = (v >= 0.f) ? v : a0v * v;
        v = acc[t][1] + b1v; acc[t][1] = (v >= 0.f) ? v : a1v * v;
        v = acc[t][2] + b0v; acc[t][2] = (v >= 0.f) ? v : a0v * v;
        v = acc[t][3] + b1v; acc[t][3] = (v >= 0.f) ? v : a1v * v;
    }

    // phase 2: += x@ws^T  (K = 64)
#pragma unroll
    for (int k = 0; k < 64; k += 8) {
        unsigned int a0 = uX[(mrow + g) * SX_STRIDE + k + tc];
        unsigned int a1 = uX[(mrow + g + 8) * SX_STRIDE + k + tc];
        unsigned int a2 = uX[(mrow + g) * SX_STRIDE + k + tc + 4];
        unsigned int a3 = uX[(mrow + g + 8) * SX_STRIDE + k + tc + 4];
#pragma unroll
        for (int t = 0; t < 4; t++) {
            int nb = ncol + t * 8;
            unsigned int b0 = uW2[(k + tc) * SW_STRIDE + nb + g];
            unsigned int b1 = uW2[(k + tc + 4) * SW_STRIDE + nb + g];
            mma_tf32(acc[t], a0, a1, a2, a3, b0, b1);
        }
    }

    // epilogue 2: + bs, paired stores
#pragma unroll
    for (int t = 0; t < 4; t++) {
        int col = ncol + t * 8 + tc * 2;
        float b0v = sBS[col], b1v = sBS[col + 1];
        int r0g = row0 + mrow + g;
        if (r0g < nrows) {
            float2 o = {acc[t][0] + b0v, acc[t][1] + b1v};
            *(float2*)(out + (size_t)r0g * 64 + col) = o;
        }
        int r1g = r0g + 8;
        if (r1g < nrows) {
            float2 o = {acc[t][2] + b0v, acc[t][3] + b1v};
            *(float2*)(out + (size_t)r1g * 64 + col) = o;
        }
    }
}

// ---------------- launch ----------------
extern "C" void kernel_launch(void* const* d_in, const int* in_sizes, int n_in,
                              void* d_out, int out_size) {
    const float* x  = (const float*)d_in[0];
    const void*  ei = d_in[1];
    const float* wl0 = (const float*)d_in[2];
    const float* bl0 = (const float*)d_in[3];
    const float* wr0 = (const float*)d_in[4];
    const float* ws0 = (const float*)d_in[5];
    const float* bs0 = (const float*)d_in[6];
    const float* a0  = (const float*)d_in[7];
    const float* wl1 = (const float*)d_in[8];
    const float* bl1 = (const float*)d_in[9];
    const float* wr1 = (const float*)d_in[10];
    const float* ws1 = (const float*)d_in[11];
    const float* bs1 = (const float*)d_in[12];
    const float* a1  = (const float*)d_in[13];
    float* out = (float*)d_out;

    int N = in_sizes[0] / 64;
    int E = in_sizes[1] / 2;

    float *agg, *h1, *inv;
    int *deg, *wcnt, *rp, *idx, *csr, *bsum;
    cudaGetSymbolAddress((void**)&agg,  g_agg);
    cudaGetSymbolAddress((void**)&h1,   g_h1);
    cudaGetSymbolAddress((void**)&deg,  g_deg);
    cudaGetSymbolAddress((void**)&wcnt, g_wcnt);
    cudaGetSymbolAddress((void**)&rp,   g_rp);
    cudaGetSymbolAddress((void**)&inv,  g_inv);
    cudaGetSymbolAddress((void**)&idx,  g_idx);
    cudaGetSymbolAddress((void**)&csr,  g_csr);
    cudaGetSymbolAddress((void**)&bsum, g_bsum);

    cudaFuncSetAttribute(sage_gemm_kernel, cudaFuncAttributeMaxDynamicSharedMemorySize, SMEM_BYTES);

    detect_kernel<<<1, 1>>>((const unsigned int*)ei);
    int total = 2 * E;
    convert_kernel<<<(total + 255) / 256, 256>>>(ei, idx, total);

    const int* src = idx;
    const int* dst = idx + E;

    // CSR build
    cudaMemsetAsync(deg,  0, (size_t)N * sizeof(int), 0);
    cudaMemsetAsync(wcnt, 0, (size_t)N * sizeof(int), 0);
    degree_kernel<<<(E + 255) / 256, 256>>>(dst, deg, E);
    inv_kernel<<<(N + 255) / 256, 256>>>(deg, inv, N);
    int nb = (N + 1023) / 1024;
    scan1_kernel<<<nb, 256>>>(deg, rp, bsum, N);
    scan2_kernel<<<1, 32>>>(bsum, nb, rp, N);
    scan3_kernel<<<(N + 255) / 256, 256>>>(rp, bsum, N);
    place_kernel<<<(E + 255) / 256, 256>>>(src, dst, rp, wcnt, csr, E);

    int gather_blocks = (N * 32 + 255) / 256;
    int gemm_blocks = (N + 63) / 64;

    // layer 0
    gather_kernel<<<gather_blocks, 256>>>((const float2*)x, rp, csr, inv, (float2*)agg, N);
    sage_gemm_kernel<<<gemm_blocks, 256, SMEM_BYTES>>>(
        agg, x, x, wl0, bl0, wr0, ws0, bs0, a0, h1, N);

    // layer 1
    gather_kernel<<<gather_blocks, 256>>>((const float2*)h1, rp, csr, inv, (float2*)agg, N);
    sage_gemm_kernel<<<gemm_blocks, 256, SMEM_BYTES>>>(
        agg, h1, x, wl1, bl1, wr1, ws1, bs1, a1, out, N);
}